// round 1
// baseline (speedup 1.0000x reference)
#include <cuda_runtime.h>

#define NATOMS 200000
#define NBONDS 400000
#define NMOLS  10000
#define AFD    133
#define BFD    13
#define HID    300
#define NTASKS 12
#define KI     146   // AFD + BFD
#define KO     433   // AFD + HID

// ---------------- device scratch (static, no runtime allocation) ----------------
__device__ float g_h0[NBONDS * HID];    // 480 MB
__device__ float g_hA[NBONDS * HID];    // 480 MB
__device__ float g_hB[NBONDS * HID];    // 480 MB
__device__ float g_amsg[NATOMS * HID];  // 240 MB
__device__ float g_ah[NATOMS * HID];    // 240 MB
__device__ float g_mol[NMOLS * HID];
__device__ float g_ro[NMOLS * HID];
__device__ int   g_tgt[NBONDS];
__device__ float g_WiT[KI * HID];
__device__ float g_WhT[HID * HID];
__device__ float g_WoT[KO * HID];
__device__ float g_Wr1T[HID * HID];

__device__ __forceinline__ float* h_buf(int s) {
    return s == 0 ? g_h0 : (s == 1 ? g_hA : g_hB);
}

// ---------------- small kernels ----------------
__global__ void transpose_k(const float* __restrict__ W, int K, int sel) {
    float* WT = sel == 0 ? g_WiT : sel == 1 ? g_WhT : sel == 2 ? g_WoT : g_Wr1T;
    int idx = blockIdx.x * blockDim.x + threadIdx.x;
    if (idx < K * HID) {
        int j = idx / K;
        int k = idx - j * K;
        WT[k * HID + j] = W[idx];
    }
}

__global__ void tgt_k(const int* __restrict__ b2a, const int* __restrict__ b2revb) {
    int i = blockIdx.x * blockDim.x + threadIdx.x;
    if (i < NBONDS) g_tgt[i] = b2a[b2revb[i]];
}

__global__ void zero_k(int sel) {
    float* p = sel == 0 ? g_amsg : g_mol;
    int n = sel == 0 ? NATOMS * HID : NMOLS * HID;
    int i = blockIdx.x * blockDim.x + threadIdx.x;
    if (i < n) p[i] = 0.f;
}

__global__ void scatter_k(int srcSel) {
    int idx = blockIdx.x * blockDim.x + threadIdx.x;
    if (idx < NBONDS * HID) {
        int b = idx / HID;
        int j = idx - b * HID;
        atomicAdd(&g_amsg[g_tgt[b] * HID + j], h_buf(srcSel)[idx]);
    }
}

__global__ void pool_k(const int* __restrict__ mol_ids) {
    int idx = blockIdx.x * blockDim.x + threadIdx.x;
    if (idx < NATOMS * HID) {
        int a = idx / HID;
        int j = idx - a * HID;
        atomicAdd(&g_mol[mol_ids[a] * HID + j], g_ah[idx]);
    }
}

__global__ void logits_k(const float* __restrict__ Wr2, const float* __restrict__ br2,
                         float* __restrict__ out) {
    int idx = blockIdx.x * blockDim.x + threadIdx.x;
    if (idx < NMOLS * NTASKS) {
        int m = idx / NTASKS;
        int t = idx - m * NTASKS;
        const float* x = &g_ro[m * HID];
        const float* w = &Wr2[t * HID];
        float s = br2[t];
#pragma unroll 4
        for (int k = 0; k < HID; k++) s += x[k] * w[k];
        out[idx] = s;
    }
}

// ---------------- fused gather-GEMM ----------------
// C[M x 300] = relu( A_gathered[M x K] @ BT[K x 300] + bias + optional h0 )
#define BM  128
#define BN  64
#define BKK 16
#define TM  8
#define TN  4

enum { MODE_H0 = 0, MODE_MSG = 1, MODE_AH = 2, MODE_RO = 3 };

template <int MODE>
__global__ __launch_bounds__(256)
void gemm_k(int M, int K, int srcSel, int dstSel,
            const float* __restrict__ fa, const float* __restrict__ fb,
            const int* __restrict__ b2a, const int* __restrict__ b2revb,
            const float* __restrict__ bias) {
    __shared__ float As[BKK][BM + 4];
    __shared__ float Bs[BKK][BN + 4];
    const int tid = threadIdx.x;
    const int tx = tid & 15;
    const int ty = tid >> 4;
    const int m0 = blockIdx.x * BM;
    const int n0 = blockIdx.y * BN;

    const float* BT = (MODE == MODE_H0)  ? g_WiT
                    : (MODE == MODE_MSG) ? g_WhT
                    : (MODE == MODE_AH)  ? g_WoT
                                         : g_Wr1T;
    const float* hsrc = (MODE == MODE_MSG) ? h_buf(srcSel) : nullptr;
    float* C = (MODE == MODE_H0)  ? g_h0
             : (MODE == MODE_MSG) ? h_buf(dstSel)
             : (MODE == MODE_AH)  ? g_ah
                                  : g_ro;

    float acc[TM][TN];
#pragma unroll
    for (int i = 0; i < TM; i++)
#pragma unroll
        for (int j = 0; j < TN; j++) acc[i][j] = 0.f;

    for (int kt = 0; kt < K; kt += BKK) {
        // ---- load A tile (gather/concat fused) ----
#pragma unroll
        for (int l = 0; l < 8; l++) {
            int e = tid + l * 256;
            int r = e >> 4;
            int kk = e & 15;
            int gm = m0 + r;
            int gk = kt + kk;
            float v = 0.f;
            if (gm < M && gk < K) {
                if (MODE == MODE_H0) {
                    v = (gk < AFD) ? fa[b2a[gm] * AFD + gk]
                                   : fb[gm * BFD + (gk - AFD)];
                } else if (MODE == MODE_MSG) {
                    v = g_amsg[b2a[gm] * HID + gk] - hsrc[b2revb[gm] * HID + gk];
                } else if (MODE == MODE_AH) {
                    v = (gk < AFD) ? fa[gm * AFD + gk]
                                   : g_amsg[gm * HID + (gk - AFD)];
                } else {
                    v = g_mol[gm * HID + gk];
                }
            }
            As[kk][r] = v;
        }
        // ---- load B tile ----
#pragma unroll
        for (int l = 0; l < 4; l++) {
            int e = tid + l * 256;
            int kk = e >> 6;
            int j = e & 63;
            int gk = kt + kk;
            int gn = n0 + j;
            Bs[kk][j] = (gk < K && gn < HID) ? BT[gk * HID + gn] : 0.f;
        }
        __syncthreads();
#pragma unroll
        for (int kk = 0; kk < BKK; kk++) {
            float ra[TM], rb[TN];
#pragma unroll
            for (int i = 0; i < TM; i++) ra[i] = As[kk][ty * TM + i];
#pragma unroll
            for (int j = 0; j < TN; j++) rb[j] = Bs[kk][tx * TN + j];
#pragma unroll
            for (int i = 0; i < TM; i++)
#pragma unroll
                for (int j = 0; j < TN; j++)
                    acc[i][j] = fmaf(ra[i], rb[j], acc[i][j]);
        }
        __syncthreads();
    }

    // ---- epilogue ----
#pragma unroll
    for (int i = 0; i < TM; i++) {
        int gm = m0 + ty * TM + i;
        if (gm >= M) continue;
#pragma unroll
        for (int j = 0; j < TN; j++) {
            int gn = n0 + tx * TN + j;
            if (gn >= HID) continue;
            float v = acc[i][j];
            if (MODE == MODE_AH || MODE == MODE_RO) v += bias[gn];
            if (MODE == MODE_MSG) v += g_h0[gm * HID + gn];
            v = fmaxf(v, 0.f);
            C[gm * HID + gn] = v;
        }
    }
}

static inline int cdiv(int a, int b) { return (a + b - 1) / b; }

extern "C" void kernel_launch(void* const* d_in, const int* in_sizes, int n_in,
                              void* d_out, int out_size) {
    const float* f_atoms = (const float*)d_in[0];
    const float* f_bonds = (const float*)d_in[1];
    const int*   b2a     = (const int*)d_in[2];
    const int*   b2revb  = (const int*)d_in[3];
    const int*   mol_ids = (const int*)d_in[4];
    const float* W_i     = (const float*)d_in[5];
    const float* W_h     = (const float*)d_in[6];
    const float* W_o     = (const float*)d_in[7];
    const float* b_o     = (const float*)d_in[8];
    const float* W_r1    = (const float*)d_in[9];
    const float* b_r1    = (const float*)d_in[10];
    const float* W_r2    = (const float*)d_in[11];
    const float* b_r2    = (const float*)d_in[12];
    float* out = (float*)d_out;

    // pre-transpose weights for coalesced B loads
    transpose_k<<<cdiv(KI * HID, 256), 256>>>(W_i, KI, 0);
    transpose_k<<<cdiv(HID * HID, 256), 256>>>(W_h, HID, 1);
    transpose_k<<<cdiv(KO * HID, 256), 256>>>(W_o, KO, 2);
    transpose_k<<<cdiv(HID * HID, 256), 256>>>(W_r1, HID, 3);
    tgt_k<<<cdiv(NBONDS, 256), 256>>>(b2a, b2revb);

    dim3 gB(cdiv(NBONDS, BM), cdiv(HID, BN));  // 3125 x 5
    dim3 gA(cdiv(NATOMS, BM), cdiv(HID, BN));  // 1563 x 5
    dim3 gM(cdiv(NMOLS, BM), cdiv(HID, BN));   // 79 x 5

    // h0 = relu(concat(f_atoms[b2a], f_bonds) @ W_i^T)
    gemm_k<MODE_H0><<<gB, 256>>>(NBONDS, KI, 0, 0, f_atoms, f_bonds, b2a, b2revb, nullptr);

    // 3 message-passing iterations (ping-pong h buffers: h0 -> hA -> hB -> hA)
    int src = 0;
    const int nxt[3] = {1, 2, 1};
    for (int d = 0; d < 3; d++) {
        zero_k<<<cdiv(NATOMS * HID, 256), 256>>>(0);
        scatter_k<<<cdiv(NBONDS * HID, 256), 256>>>(src);
        gemm_k<MODE_MSG><<<gB, 256>>>(NBONDS, HID, src, nxt[d], nullptr, nullptr, b2a, b2revb, nullptr);
        src = nxt[d];
    }

    // final aggregation
    zero_k<<<cdiv(NATOMS * HID, 256), 256>>>(0);
    scatter_k<<<cdiv(NBONDS * HID, 256), 256>>>(src);

    // atom_h = relu(concat(f_atoms, atom_msg) @ W_o^T + b_o)
    gemm_k<MODE_AH><<<gA, 256>>>(NATOMS, KO, 0, 0, f_atoms, nullptr, nullptr, nullptr, b_o);

    // per-molecule sum pooling
    zero_k<<<cdiv(NMOLS * HID, 256), 256>>>(1);
    pool_k<<<cdiv(NATOMS * HID, 256), 256>>>(mol_ids);

    // readout
    gemm_k<MODE_RO><<<gM, 256>>>(NMOLS, HID, 0, 0, nullptr, nullptr, nullptr, nullptr, b_r1);
    logits_k<<<cdiv(NMOLS * NTASKS, 256), 256>>>(W_r2, b_r2, out);
}

// round 2
// speedup vs baseline: 1.3669x; 1.3669x over previous
#include <cuda_runtime.h>
#include <cstdint>

#define NATOMS 200000
#define NBONDS 400000
#define NMOLS  10000
#define AFD    133
#define BFD    13
#define HID    300
#define NTASKS 12
#define KI     146   // AFD + BFD
#define KO     433   // AFD + HID

// ---------------- device scratch (static, no runtime allocation) ----------------
__device__ float g_h0[NBONDS * HID];
__device__ float g_hA[NBONDS * HID];
__device__ float g_hB[NBONDS * HID];
__device__ float g_amsg[NATOMS * HID];
__device__ float g_ah[NATOMS * HID];
__device__ float g_mol[NMOLS * HID];
__device__ float g_ro[NMOLS * HID];
__device__ int   g_tgt[NBONDS];
__device__ float g_WiT[KI * HID];
__device__ float g_WhT[HID * HID];
__device__ float g_WoT[KO * HID];
__device__ float g_Wr1T[HID * HID];

__device__ __forceinline__ float* h_buf(int s) {
    return s == 0 ? g_h0 : (s == 1 ? g_hA : g_hB);
}

__device__ __forceinline__ uint32_t tf32_bits(float v) {
    uint32_t r;
    asm("cvt.rna.tf32.f32 %0, %1;" : "=r"(r) : "f"(v));
    return r;
}

// ---------------- small kernels ----------------
__global__ void transpose_k(const float* __restrict__ W, int K, int sel) {
    float* WT = sel == 0 ? g_WiT : sel == 1 ? g_WhT : sel == 2 ? g_WoT : g_Wr1T;
    int idx = blockIdx.x * blockDim.x + threadIdx.x;
    if (idx < K * HID) {
        int j = idx / K;
        int k = idx - j * K;
        WT[k * HID + j] = W[idx];
    }
}

__global__ void tgt_k(const int* __restrict__ b2a, const int* __restrict__ b2revb) {
    int i = blockIdx.x * blockDim.x + threadIdx.x;
    if (i < NBONDS) g_tgt[i] = b2a[b2revb[i]];
}

__global__ void zero_k(int sel) {
    float* p = sel == 0 ? g_amsg : g_mol;
    int n = sel == 0 ? NATOMS * HID : NMOLS * HID;
    int i = blockIdx.x * blockDim.x + threadIdx.x;
    if (i < n) p[i] = 0.f;
}

// scatter-add bond messages to atoms (float4 loads, 4 REDGs each)
__global__ void scatter_k(int srcSel) {
    int idx = blockIdx.x * blockDim.x + threadIdx.x;
    const int NQ = HID / 4;  // 75
    if (idx < NBONDS * NQ) {
        int b = idx / NQ;
        int q = idx - b * NQ;
        float4 v = reinterpret_cast<const float4*>(h_buf(srcSel))[idx];
        float* dst = &g_amsg[g_tgt[b] * HID + q * 4];
        atomicAdd(dst + 0, v.x);
        atomicAdd(dst + 1, v.y);
        atomicAdd(dst + 2, v.z);
        atomicAdd(dst + 3, v.w);
    }
}

__global__ void pool_k(const int* __restrict__ mol_ids) {
    int idx = blockIdx.x * blockDim.x + threadIdx.x;
    const int NQ = HID / 4;
    if (idx < NATOMS * NQ) {
        int a = idx / NQ;
        int q = idx - a * NQ;
        float4 v = reinterpret_cast<const float4*>(g_ah)[idx];
        float* dst = &g_mol[mol_ids[a] * HID + q * 4];
        atomicAdd(dst + 0, v.x);
        atomicAdd(dst + 1, v.y);
        atomicAdd(dst + 2, v.z);
        atomicAdd(dst + 3, v.w);
    }
}

__global__ void logits_k(const float* __restrict__ Wr2, const float* __restrict__ br2,
                         float* __restrict__ out) {
    int idx = blockIdx.x * blockDim.x + threadIdx.x;
    if (idx < NMOLS * NTASKS) {
        int m = idx / NTASKS;
        int t = idx - m * NTASKS;
        const float* x = &g_ro[m * HID];
        const float* w = &Wr2[t * HID];
        float s = br2[t];
#pragma unroll 4
        for (int k = 0; k < HID; k++) s += x[k] * w[k];
        out[idx] = s;
    }
}

// ---------------- fused gather-GEMM on tensor cores (tf32 mma.sync) ----------------
// C[M x 300] = relu( A_gathered[M x K] @ BT[K x 300] + bias + optional h0 )
#define BM  128
#define BN  64
#define BKK 16

enum { MODE_H0 = 0, MODE_MSG = 1, MODE_AH = 2, MODE_RO = 3 };

template <int MODE>
__global__ __launch_bounds__(256)
void gemm_k(int M, int K, int srcSel, int dstSel,
            const float* __restrict__ fa, const float* __restrict__ fb,
            const int* __restrict__ b2a, const int* __restrict__ b2revb,
            const float* __restrict__ bias) {
    __shared__ uint32_t As[BKK][BM + 4];
    __shared__ uint32_t Bs[BKK][BN + 4];
    const int tid = threadIdx.x;
    const int m0 = blockIdx.y * BM;      // M on y (N-tiles adjacent in x for L2 reuse of A)
    const int n0 = blockIdx.x * BN;

    const int lane = tid & 31;
    const int g    = lane >> 2;          // 0..7
    const int tig  = lane & 3;           // 0..3
    const int wid  = tid >> 5;           // 0..7
    const int wm   = wid & 3;            // warp M index (4)
    const int wn   = wid >> 2;           // warp N index (2)
    const int mrow = wm * 32;
    const int ncol = wn * 32;

    const float* BT = (MODE == MODE_H0)  ? g_WiT
                    : (MODE == MODE_MSG) ? g_WhT
                    : (MODE == MODE_AH)  ? g_WoT
                                         : g_Wr1T;
    const float* hsrc = (MODE == MODE_MSG) ? h_buf(srcSel) : nullptr;
    float* C = (MODE == MODE_H0)  ? g_h0
             : (MODE == MODE_MSG) ? h_buf(dstSel)
             : (MODE == MODE_AH)  ? g_ah
                                  : g_ro;

    float acc[2][4][4];
#pragma unroll
    for (int mi = 0; mi < 2; mi++)
#pragma unroll
        for (int ni = 0; ni < 4; ni++)
#pragma unroll
            for (int c = 0; c < 4; c++) acc[mi][ni][c] = 0.f;

    for (int kt = 0; kt < K; kt += BKK) {
        // ---- load A tile (gather/concat fused), convert to tf32 ----
#pragma unroll
        for (int l = 0; l < 8; l++) {
            int e = tid + l * 256;
            int r = e >> 4;
            int kk = e & 15;
            int gm = m0 + r;
            int gk = kt + kk;
            float v = 0.f;
            if (gm < M && gk < K) {
                if (MODE == MODE_H0) {
                    v = (gk < AFD) ? fa[b2a[gm] * AFD + gk]
                                   : fb[gm * BFD + (gk - AFD)];
                } else if (MODE == MODE_MSG) {
                    v = g_amsg[b2a[gm] * HID + gk] - hsrc[b2revb[gm] * HID + gk];
                } else if (MODE == MODE_AH) {
                    v = (gk < AFD) ? fa[gm * AFD + gk]
                                   : g_amsg[gm * HID + (gk - AFD)];
                } else {
                    v = g_mol[gm * HID + gk];
                }
            }
            As[kk][r] = tf32_bits(v);
        }
        // ---- load B tile ----
#pragma unroll
        for (int l = 0; l < 4; l++) {
            int e = tid + l * 256;
            int kk = e >> 6;
            int j = e & 63;
            int gk = kt + kk;
            int gn = n0 + j;
            float v = (gk < K && gn < HID) ? BT[gk * HID + gn] : 0.f;
            Bs[kk][j] = tf32_bits(v);
        }
        __syncthreads();

#pragma unroll
        for (int ks = 0; ks < 2; ks++) {
            const int k0 = ks * 8;
            uint32_t afr[2][4];
#pragma unroll
            for (int mi = 0; mi < 2; mi++) {
                int r0 = mrow + mi * 16 + g;
                afr[mi][0] = As[k0 + tig][r0];
                afr[mi][1] = As[k0 + tig][r0 + 8];
                afr[mi][2] = As[k0 + tig + 4][r0];
                afr[mi][3] = As[k0 + tig + 4][r0 + 8];
            }
            uint32_t bfr[4][2];
#pragma unroll
            for (int ni = 0; ni < 4; ni++) {
                int c0 = ncol + ni * 8 + g;
                bfr[ni][0] = Bs[k0 + tig][c0];
                bfr[ni][1] = Bs[k0 + tig + 4][c0];
            }
#pragma unroll
            for (int mi = 0; mi < 2; mi++)
#pragma unroll
                for (int ni = 0; ni < 4; ni++) {
                    asm volatile(
                        "mma.sync.aligned.m16n8k8.row.col.f32.tf32.tf32.f32 "
                        "{%0,%1,%2,%3}, {%4,%5,%6,%7}, {%8,%9}, {%0,%1,%2,%3};"
                        : "+f"(acc[mi][ni][0]), "+f"(acc[mi][ni][1]),
                          "+f"(acc[mi][ni][2]), "+f"(acc[mi][ni][3])
                        : "r"(afr[mi][0]), "r"(afr[mi][1]),
                          "r"(afr[mi][2]), "r"(afr[mi][3]),
                          "r"(bfr[ni][0]), "r"(bfr[ni][1]));
                }
        }
        __syncthreads();
    }

    // ---- epilogue ----
#pragma unroll
    for (int mi = 0; mi < 2; mi++) {
#pragma unroll
        for (int ni = 0; ni < 4; ni++) {
            int col = n0 + ncol + ni * 8 + tig * 2;
#pragma unroll
            for (int half = 0; half < 2; half++) {
                int row = m0 + mrow + mi * 16 + g + half * 8;
                if (row >= M) continue;
#pragma unroll
                for (int cc = 0; cc < 2; cc++) {
                    int gn = col + cc;
                    if (gn >= HID) continue;
                    float v = acc[mi][ni][half * 2 + cc];
                    if (MODE == MODE_AH || MODE == MODE_RO) v += bias[gn];
                    if (MODE == MODE_MSG) v += g_h0[row * HID + gn];
                    v = fmaxf(v, 0.f);
                    C[row * HID + gn] = v;
                }
            }
        }
    }
}

static inline int cdiv(int a, int b) { return (a + b - 1) / b; }

extern "C" void kernel_launch(void* const* d_in, const int* in_sizes, int n_in,
                              void* d_out, int out_size) {
    const float* f_atoms = (const float*)d_in[0];
    const float* f_bonds = (const float*)d_in[1];
    const int*   b2a     = (const int*)d_in[2];
    const int*   b2revb  = (const int*)d_in[3];
    const int*   mol_ids = (const int*)d_in[4];
    const float* W_i     = (const float*)d_in[5];
    const float* W_h     = (const float*)d_in[6];
    const float* W_o     = (const float*)d_in[7];
    const float* b_o     = (const float*)d_in[8];
    const float* W_r1    = (const float*)d_in[9];
    const float* b_r1    = (const float*)d_in[10];
    const float* W_r2    = (const float*)d_in[11];
    const float* b_r2    = (const float*)d_in[12];
    float* out = (float*)d_out;

    transpose_k<<<cdiv(KI * HID, 256), 256>>>(W_i, KI, 0);
    transpose_k<<<cdiv(HID * HID, 256), 256>>>(W_h, HID, 1);
    transpose_k<<<cdiv(KO * HID, 256), 256>>>(W_o, KO, 2);
    transpose_k<<<cdiv(HID * HID, 256), 256>>>(W_r1, HID, 3);
    tgt_k<<<cdiv(NBONDS, 256), 256>>>(b2a, b2revb);

    dim3 gB(cdiv(HID, BN), cdiv(NBONDS, BM));  // 5 x 3125
    dim3 gA(cdiv(HID, BN), cdiv(NATOMS, BM));  // 5 x 1563
    dim3 gM(cdiv(HID, BN), cdiv(NMOLS, BM));   // 5 x 79

    // h0 = relu(concat(f_atoms[b2a], f_bonds) @ W_i^T)
    gemm_k<MODE_H0><<<gB, 256>>>(NBONDS, KI, 0, 0, f_atoms, f_bonds, b2a, b2revb, nullptr);

    // 3 message-passing iterations (ping-pong h buffers: h0 -> hA -> hB -> hA)
    int src = 0;
    const int nxt[3] = {1, 2, 1};
    const int NQ = HID / 4;
    for (int d = 0; d < 3; d++) {
        zero_k<<<cdiv(NATOMS * HID, 256), 256>>>(0);
        scatter_k<<<cdiv(NBONDS * NQ, 256), 256>>>(src);
        gemm_k<MODE_MSG><<<gB, 256>>>(NBONDS, HID, src, nxt[d], nullptr, nullptr, b2a, b2revb, nullptr);
        src = nxt[d];
    }

    // final aggregation
    zero_k<<<cdiv(NATOMS * HID, 256), 256>>>(0);
    scatter_k<<<cdiv(NBONDS * NQ, 256), 256>>>(src);

    // atom_h = relu(concat(f_atoms, atom_msg) @ W_o^T + b_o)
    gemm_k<MODE_AH><<<gA, 256>>>(NATOMS, KO, 0, 0, f_atoms, nullptr, nullptr, nullptr, b_o);

    // per-molecule sum pooling
    zero_k<<<cdiv(NMOLS * HID, 256), 256>>>(1);
    pool_k<<<cdiv(NATOMS * NQ, 256), 256>>>(mol_ids);

    // readout
    gemm_k<MODE_RO><<<gM, 256>>>(NMOLS, HID, 0, 0, nullptr, nullptr, nullptr, nullptr, b_r1);
    logits_k<<<cdiv(NMOLS * NTASKS, 256), 256>>>(W_r2, b_r2, out);
}

// round 4
// speedup vs baseline: 1.9009x; 1.3907x over previous
#include <cuda_runtime.h>
#include <cstdint>

#define NATOMS 200000
#define NBONDS 400000
#define NMOLS  10000
#define AFD    133
#define BFD    13
#define HID    300
#define NTASKS 12
#define KI     146
#define KO     433
#define SP     304      // padded row stride for all feature buffers
#define WSTR   320      // padded row stride for transposed weights
#define KP_H0  160
#define KP_MSG 304
#define KP_AH  448
#define KP_RO  304

// ---------------- device scratch (static; zero-initialized at module load) ----------------
__device__ float g_h0[(size_t)NBONDS * SP];
__device__ float g_hA[(size_t)NBONDS * SP];
__device__ float g_hB[(size_t)NBONDS * SP];
__device__ float g_amsg[(size_t)NATOMS * SP];
__device__ float g_ah[(size_t)NATOMS * SP];
__device__ float g_mol[(size_t)NMOLS * SP];
__device__ float g_ro[(size_t)NMOLS * SP];
__device__ int   g_tgt[NBONDS];
__device__ int   g_cnt[NATOMS];
__device__ int   g_off[NATOMS + 1];
__device__ int   g_cur[NATOMS];
__device__ int   g_idx[NBONDS];
__device__ int   g_mstart[NMOLS + 1];
__device__ uint32_t g_WiT[KP_H0 * WSTR];    // tf32 bits, zero-padded
__device__ uint32_t g_WhT[KP_MSG * WSTR];
__device__ uint32_t g_WoT[KP_AH * WSTR];
__device__ uint32_t g_Wr1T[KP_RO * WSTR];

__device__ __forceinline__ float* h_buf(int s) {
    return s == 0 ? g_h0 : (s == 1 ? g_hA : g_hB);
}
__device__ __forceinline__ uint32_t tf32_bits(float v) {
    uint32_t r;
    asm("cvt.rna.tf32.f32 %0, %1;" : "=r"(r) : "f"(v));
    return r;
}
__device__ __forceinline__ uint32_t smem_u32(const void* p) {
    return (uint32_t)__cvta_generic_to_shared(p);
}

// ---------------- prep kernels ----------------
__global__ void transpose_k(const float* __restrict__ W, int K, int sel) {
    uint32_t* WT = sel == 0 ? g_WiT : sel == 1 ? g_WhT : sel == 2 ? g_WoT : g_Wr1T;
    int idx = blockIdx.x * blockDim.x + threadIdx.x;
    if (idx < K * HID) {
        int j = idx / K;          // output col (0..299)
        int k = idx - j * K;      // k row
        WT[k * WSTR + j] = tf32_bits(W[idx]);
    }
}

__global__ void tgt_hist_k(const int* __restrict__ b2a, const int* __restrict__ b2revb) {
    int i = blockIdx.x * blockDim.x + threadIdx.x;
    if (i < NBONDS) {
        int t = b2a[b2revb[i]];
        g_tgt[i] = t;
        atomicAdd(&g_cnt[t], 1);
    }
}

__global__ void zerocnt_k() {
    int i = blockIdx.x * blockDim.x + threadIdx.x;
    if (i < NATOMS) g_cnt[i] = 0;
}

// single-block exclusive scan of g_cnt -> g_off/g_cur (1024 threads)
__global__ void scan_k() {
    __shared__ int sh[1024];
    const int per = (NATOMS + 1023) / 1024;
    int t = threadIdx.x;
    int s0 = t * per;
    int e0 = min(s0 + per, NATOMS);
    int sum = 0;
    for (int i = s0; i < e0; i++) sum += g_cnt[i];
    sh[t] = sum;
    __syncthreads();
    for (int off = 1; off < 1024; off <<= 1) {
        int v = (t >= off) ? sh[t - off] : 0;
        __syncthreads();
        sh[t] += v;
        __syncthreads();
    }
    int run = (t == 0) ? 0 : sh[t - 1];
    for (int i = s0; i < e0; i++) {
        int c = g_cnt[i];
        g_off[i] = run;
        g_cur[i] = run;
        run += c;
    }
    if (t == 1023) g_off[NATOMS] = NBONDS;
}

__global__ void fill_k() {
    int b = blockIdx.x * blockDim.x + threadIdx.x;
    if (b < NBONDS) {
        int a = g_tgt[b];
        int p = atomicAdd(&g_cur[a], 1);
        g_idx[p] = b;
    }
}

__global__ void mstart_k(const int* __restrict__ mol_ids) {
    int a = blockIdx.x * blockDim.x + threadIdx.x;
    if (a < NATOMS) {
        int id = mol_ids[a];
        int prev = (a == 0) ? -1 : mol_ids[a - 1];
        for (int m = prev + 1; m <= id; m++) g_mstart[m] = a;
        if (a == NATOMS - 1)
            for (int m = id + 1; m <= NMOLS; m++) g_mstart[m] = NATOMS;
    }
}

// ---------------- CSR gather aggregations (replace atomic scatters) ----------------
#define NQ 75  // real float4 chunks per row (300/4)

__global__ void agg_k(int srcSel) {
    int t = blockIdx.x * blockDim.x + threadIdx.x;
    if (t >= NATOMS * NQ) return;
    int a = t / NQ;
    int q = t - a * NQ;
    int s = g_off[a], e = g_off[a + 1];
    const float* h = h_buf(srcSel);
    float4 acc = make_float4(0.f, 0.f, 0.f, 0.f);
    for (int i = s; i < e; i++) {
        int b = g_idx[i];
        float4 v = *(const float4*)(h + (size_t)b * SP + q * 4);
        acc.x += v.x; acc.y += v.y; acc.z += v.z; acc.w += v.w;
    }
    *(float4*)(g_amsg + (size_t)a * SP + q * 4) = acc;
}

__global__ void poolagg_k() {
    int t = blockIdx.x * blockDim.x + threadIdx.x;
    if (t >= NMOLS * NQ) return;
    int m = t / NQ;
    int q = t - m * NQ;
    int s = g_mstart[m], e = g_mstart[m + 1];
    float4 acc = make_float4(0.f, 0.f, 0.f, 0.f);
    for (int a = s; a < e; a++) {
        float4 v = *(const float4*)(g_ah + (size_t)a * SP + q * 4);
        acc.x += v.x; acc.y += v.y; acc.z += v.z; acc.w += v.w;
    }
    *(float4*)(g_mol + (size_t)m * SP + q * 4) = acc;
}

__global__ void logits_k(const float* __restrict__ Wr2, const float* __restrict__ br2,
                         float* __restrict__ out) {
    int idx = blockIdx.x * blockDim.x + threadIdx.x;
    if (idx < NMOLS * NTASKS) {
        int m = idx / NTASKS;
        int t = idx - m * NTASKS;
        const float* x = &g_ro[(size_t)m * SP];
        const float* w = &Wr2[t * HID];
        float s = br2[t];
#pragma unroll 4
        for (int k = 0; k < HID; k++) s += x[k] * w[k];
        out[idx] = s;
    }
}

// ---------------- fused gather-GEMM (tf32 mma.sync, double-buffered) ----------------
#define BM   256
#define BN   64
#define BKK  16
#define ASTR 264   // 256+8 -> stride mod 32 == 8 -> conflict-free fragments
#define BSTR 72    // 64+8

enum { MODE_H0 = 0, MODE_MSG = 1, MODE_AH = 2, MODE_RO = 3 };

template <int MODE>
__global__ __launch_bounds__(256)
void gemm_k(int M, int srcSel, int dstSel,
            const float* __restrict__ fa, const float* __restrict__ fb,
            const int* __restrict__ b2a, const int* __restrict__ b2revb,
            const float* __restrict__ bias) {
    __shared__ uint32_t As[2][BKK][ASTR];
    __shared__ uint32_t Bs[2][BKK][BSTR];

    const int tid  = threadIdx.x;
    const int lane = tid & 31;
    const int wid  = tid >> 5;
    const int g    = lane >> 2;
    const int tig  = lane & 3;
    const int wm   = wid & 3;    // 4 warps along M
    const int wn   = wid >> 2;   // 2 warps along N
    const int mrow = wm * 64;
    const int ncol = wn * 32;
    const int n0   = blockIdx.x * BN;
    const int m0   = blockIdx.y * BM;

    const int Kpad = (MODE == MODE_H0) ? KP_H0 : (MODE == MODE_MSG) ? KP_MSG
                   : (MODE == MODE_AH) ? KP_AH : KP_RO;
    const uint32_t* BT = (MODE == MODE_H0)  ? g_WiT
                       : (MODE == MODE_MSG) ? g_WhT
                       : (MODE == MODE_AH)  ? g_WoT
                                            : g_Wr1T;
    float* C = (MODE == MODE_H0)  ? g_h0
             : (MODE == MODE_MSG) ? h_buf(dstSel)
             : (MODE == MODE_AH)  ? g_ah
                                  : g_ro;

    // per-thread A row
    const int gm  = m0 + tid;
    const bool rv = gm < M;
    const int gmc = rv ? gm : 0;
    int ia = 0, ih = 0;
    if (MODE == MODE_H0 || MODE == MODE_MSG) ia = rv ? b2a[gm] : 0;
    if (MODE == MODE_MSG) ih = rv ? b2revb[gm] : 0;

    const float* arow = nullptr;
    const float* hrow = nullptr;
    if (MODE == MODE_MSG) {
        arow = g_amsg + (size_t)ia * SP;
        hrow = h_buf(srcSel) + (size_t)ih * SP;
    } else if (MODE == MODE_RO) {
        arow = g_mol + (size_t)gmc * SP;
    }

    // B cp.async assignment: 256 threads x 16B covers 16x64 tile
    const int bkk = tid >> 4;
    const int bj  = (tid & 15) * 4;
    const uint32_t* bsrc0 = BT + (size_t)bkk * WSTR + n0 + bj;

    float acc[4][4][4];
#pragma unroll
    for (int mi = 0; mi < 4; mi++)
#pragma unroll
        for (int ni = 0; ni < 4; ni++)
#pragma unroll
            for (int c = 0; c < 4; c++) acc[mi][ni][c] = 0.f;

    float4 xa[4], xh[4];
    float  vs[16];

    auto stage = [&](int t) {
        const int kt = t * BKK;
        if (MODE == MODE_MSG) {
            const float4* pa = (const float4*)(arow + kt);
            const float4* ph = (const float4*)(hrow + kt);
#pragma unroll
            for (int q = 0; q < 4; q++) { xa[q] = pa[q]; xh[q] = ph[q]; }
        } else if (MODE == MODE_RO) {
            const float4* pa = (const float4*)(arow + kt);
#pragma unroll
            for (int q = 0; q < 4; q++) xa[q] = pa[q];
        } else if (MODE == MODE_H0) {
#pragma unroll
            for (int j = 0; j < 16; j++) {
                int gk = kt + j;
                vs[j] = (gk < AFD) ? fa[(size_t)ia * AFD + gk]
                      : (gk < KI)  ? fb[(size_t)gmc * BFD + (gk - AFD)]
                                   : 0.f;
            }
        } else {  // MODE_AH
#pragma unroll
            for (int j = 0; j < 16; j++) {
                int gk = kt + j;
                vs[j] = (gk < AFD) ? fa[(size_t)gmc * AFD + gk]
                      : (gk < KO)  ? g_amsg[(size_t)gmc * SP + (gk - AFD)]
                                   : 0.f;
            }
        }
    };

    auto storeA = [&](int buf) {
        if (MODE == MODE_MSG) {
#pragma unroll
            for (int q = 0; q < 4; q++) {
                As[buf][q * 4 + 0][tid] = tf32_bits(xa[q].x - xh[q].x);
                As[buf][q * 4 + 1][tid] = tf32_bits(xa[q].y - xh[q].y);
                As[buf][q * 4 + 2][tid] = tf32_bits(xa[q].z - xh[q].z);
                As[buf][q * 4 + 3][tid] = tf32_bits(xa[q].w - xh[q].w);
            }
        } else if (MODE == MODE_RO) {
#pragma unroll
            for (int q = 0; q < 4; q++) {
                As[buf][q * 4 + 0][tid] = tf32_bits(xa[q].x);
                As[buf][q * 4 + 1][tid] = tf32_bits(xa[q].y);
                As[buf][q * 4 + 2][tid] = tf32_bits(xa[q].z);
                As[buf][q * 4 + 3][tid] = tf32_bits(xa[q].w);
            }
        } else {
#pragma unroll
            for (int j = 0; j < 16; j++) As[buf][j][tid] = tf32_bits(vs[j]);
        }
    };

    auto cpB = [&](int t, int buf) {
        const uint32_t* src = bsrc0 + (size_t)t * BKK * WSTR;
        uint32_t dst = smem_u32(&Bs[buf][bkk][bj]);
        asm volatile("cp.async.cg.shared.global [%0], [%1], 16;\n" :: "r"(dst), "l"(src));
    };

    auto domma = [&](int buf) {
#pragma unroll
        for (int ks = 0; ks < 2; ks++) {
            const int k0 = ks * 8;
            uint32_t bfr[4][2];
#pragma unroll
            for (int ni = 0; ni < 4; ni++) {
                int c0 = ncol + ni * 8 + g;
                bfr[ni][0] = Bs[buf][k0 + tig][c0];
                bfr[ni][1] = Bs[buf][k0 + tig + 4][c0];
            }
#pragma unroll
            for (int mi = 0; mi < 4; mi++) {
                int r0 = mrow + mi * 16 + g;
                uint32_t a0 = As[buf][k0 + tig][r0];
                uint32_t a1 = As[buf][k0 + tig][r0 + 8];
                uint32_t a2 = As[buf][k0 + tig + 4][r0];
                uint32_t a3 = As[buf][k0 + tig + 4][r0 + 8];
#pragma unroll
                for (int ni = 0; ni < 4; ni++) {
                    asm volatile(
                        "mma.sync.aligned.m16n8k8.row.col.f32.tf32.tf32.f32 "
                        "{%0,%1,%2,%3}, {%4,%5,%6,%7}, {%8,%9}, {%0,%1,%2,%3};"
                        : "+f"(acc[mi][ni][0]), "+f"(acc[mi][ni][1]),
                          "+f"(acc[mi][ni][2]), "+f"(acc[mi][ni][3])
                        : "r"(a0), "r"(a1), "r"(a2), "r"(a3),
                          "r"(bfr[ni][0]), "r"(bfr[ni][1]));
                }
            }
        }
    };

    const int T = Kpad / BKK;

    // prologue: tile 0
    stage(0);
    cpB(0, 0);
    asm volatile("cp.async.commit_group;\n" ::: "memory");
    storeA(0);
    asm volatile("cp.async.wait_group 0;\n" ::: "memory");
    __syncthreads();

    for (int t = 0; t < T; t++) {
        const int cur = t & 1;
        const int nxt = cur ^ 1;
        const bool more = (t + 1 < T);
        if (more) {
            stage(t + 1);
            cpB(t + 1, nxt);
            asm volatile("cp.async.commit_group;\n" ::: "memory");
        }
        domma(cur);
        __syncthreads();
        if (more) {
            storeA(nxt);
            asm volatile("cp.async.wait_group 0;\n" ::: "memory");
            __syncthreads();
        }
    }

    // ---- epilogue ----
#pragma unroll
    for (int mi = 0; mi < 4; mi++) {
#pragma unroll
        for (int ni = 0; ni < 4; ni++) {
            int col = n0 + ncol + ni * 8 + tig * 2;
#pragma unroll
            for (int half = 0; half < 2; half++) {
                int row = m0 + mrow + mi * 16 + g + half * 8;
                if (row >= M) continue;
#pragma unroll
                for (int cc = 0; cc < 2; cc++) {
                    int gn = col + cc;
                    if (gn >= HID) continue;
                    float v = acc[mi][ni][half * 2 + cc];
                    if (MODE == MODE_AH || MODE == MODE_RO) v += bias[gn];
                    if (MODE == MODE_MSG) v += g_h0[(size_t)row * SP + gn];
                    v = fmaxf(v, 0.f);
                    C[(size_t)row * SP + gn] = v;
                }
            }
        }
    }
}

static inline int cdiv(int a, int b) { return (a + b - 1) / b; }

extern "C" void kernel_launch(void* const* d_in, const int* in_sizes, int n_in,
                              void* d_out, int out_size) {
    const float* f_atoms = (const float*)d_in[0];
    const float* f_bonds = (const float*)d_in[1];
    const int*   b2a     = (const int*)d_in[2];
    const int*   b2revb  = (const int*)d_in[3];
    const int*   mol_ids = (const int*)d_in[4];
    const float* W_i     = (const float*)d_in[5];
    const float* W_h     = (const float*)d_in[6];
    const float* W_o     = (const float*)d_in[7];
    const float* b_o     = (const float*)d_in[8];
    const float* W_r1    = (const float*)d_in[9];
    const float* b_r1    = (const float*)d_in[10];
    const float* W_r2    = (const float*)d_in[11];
    const float* b_r2    = (const float*)d_in[12];
    float* out = (float*)d_out;

    // weights -> tf32-bit transposed, padded
    transpose_k<<<cdiv(KI * HID, 256), 256>>>(W_i, KI, 0);
    transpose_k<<<cdiv(HID * HID, 256), 256>>>(W_h, HID, 1);
    transpose_k<<<cdiv(KO * HID, 256), 256>>>(W_o, KO, 2);
    transpose_k<<<cdiv(HID * HID, 256), 256>>>(W_r1, HID, 3);

    // CSR build (bond -> target atom)
    zerocnt_k<<<cdiv(NATOMS, 256), 256>>>();
    tgt_hist_k<<<cdiv(NBONDS, 256), 256>>>(b2a, b2revb);
    scan_k<<<1, 1024>>>();
    fill_k<<<cdiv(NBONDS, 256), 256>>>();
    mstart_k<<<cdiv(NATOMS, 256), 256>>>(mol_ids);

    dim3 gB(5, cdiv(NBONDS, BM));   // 5 x 1563
    dim3 gA(5, cdiv(NATOMS, BM));   // 5 x 782
    dim3 gM(5, cdiv(NMOLS, BM));    // 5 x 40

    // h0 = relu(concat(f_atoms[b2a], f_bonds) @ W_i^T)
    gemm_k<MODE_H0><<<gB, 256>>>(NBONDS, 0, 0, f_atoms, f_bonds, b2a, b2revb, nullptr);

    // 3 message-passing iterations (h0 -> hA -> hB -> hA)
    int src = 0;
    const int nxt[3] = {1, 2, 1};
    for (int d = 0; d < 3; d++) {
        agg_k<<<cdiv(NATOMS * NQ, 256), 256>>>(src);
        gemm_k<MODE_MSG><<<gB, 256>>>(NBONDS, src, nxt[d], nullptr, nullptr, b2a, b2revb, nullptr);
        src = nxt[d];
    }

    // final aggregation + atom output
    agg_k<<<cdiv(NATOMS * NQ, 256), 256>>>(src);
    gemm_k<MODE_AH><<<gA, 256>>>(NATOMS, 0, 0, f_atoms, nullptr, nullptr, nullptr, b_o);

    // per-molecule pooling (sorted mol_ids -> contiguous ranges)
    poolagg_k<<<cdiv(NMOLS * NQ, 256), 256>>>();

    // readout
    gemm_k<MODE_RO><<<gM, 256>>>(NMOLS, 0, 0, nullptr, nullptr, nullptr, nullptr, b_r1);
    logits_k<<<cdiv(NMOLS * NTASKS, 256), 256>>>(W_r2, b_r2, out);
}